// round 6
// baseline (speedup 1.0000x reference)
#include <cuda_runtime.h>
#include <cuda_fp16.h>
#include <math.h>

// Problem constants (fixed by the dataset)
#define Bc   4
#define Nc   50000
#define EcMax 800000
#define INc  128
#define Hc   4
#define Dc   32
#define HDc  128
#define BNc  (Bc * Nc)          // 200000 rows
#define GAT_SLOPE 0.2f
#define ACT_SLOPE 0.01f
#define BN_EPS    1e-5f

// ---------------- scratch (device globals; no allocation allowed) ----------
// Invariant discipline: every global that must be zero at kernel-launch entry
// is zeroed by the kernel that CONSUMES it, so graph replays are deterministic.
__device__ __half   g_featH[(size_t)BNc * HDc]; // 51.2 MB (fp16 features)
__device__ float4   g_el[BNc];                  // per-node, per-head (4 heads)
__device__ float4   g_er[BNc];
__device__ int      g_cnt[Nc];                  // in-degree histogram (zeroed by k_scan)
__device__ int      g_off[Nc + 1];              // CSR offsets
__device__ int      g_wr[Nc];                   // scatter write cursors
__device__ int      g_csrc[EcMax];              // CSR: src node per slot
__device__ float    g_sum[HDc];                 // zeroed by k_bnfinal
__device__ float    g_sq[HDc];                  // zeroed by k_bnfinal
__device__ float    g_scale[HDc];
__device__ float    g_shift[HDc];

__device__ __forceinline__ float leaky(float v, float s) {
    return v >= 0.0f ? v : s * v;
}

__device__ __forceinline__ unsigned f2tf32(float f) {
    unsigned u;
    asm("cvt.rna.tf32.f32 %0, %1;" : "=r"(u) : "f"(f));
    return u;
}

__device__ __forceinline__ void mma_tf32(float* c, const unsigned* a,
                                         unsigned b0, unsigned b1) {
    asm volatile(
        "mma.sync.aligned.m16n8k8.row.col.f32.tf32.tf32.f32 "
        "{%0,%1,%2,%3}, {%4,%5,%6,%7}, {%8,%9}, {%0,%1,%2,%3};"
        : "+f"(c[0]), "+f"(c[1]), "+f"(c[2]), "+f"(c[3])
        : "r"(a[0]), "r"(a[1]), "r"(a[2]), "r"(a[3]), "r"(b0), "r"(b1));
}

// ---------------- CSR build --------------------------------------------------
__global__ void k_hist(const int* __restrict__ dst, int E) {
    int e = blockIdx.x * blockDim.x + threadIdx.x;
    if (e < E) atomicAdd(&g_cnt[dst[e]], 1);
}

// single block, 1024 threads: exclusive scan of g_cnt -> g_off/g_wr,
// then restore g_cnt to zero (consumes the histogram).
__global__ void k_scan() {
    __shared__ int ssum[1024];
    const int t = threadIdx.x;
    const int per = (Nc + 1023) / 1024;   // 49
    const int base = t * per;
    int s = 0;
    for (int i = 0; i < per; i++) {
        int idx = base + i;
        if (idx < Nc) s += g_cnt[idx];
    }
    ssum[t] = s;
    __syncthreads();
    for (int o = 1; o < 1024; o <<= 1) {
        int v = (t >= o) ? ssum[t - o] : 0;
        __syncthreads();
        ssum[t] += v;
        __syncthreads();
    }
    int run = ssum[t] - s;
    for (int i = 0; i < per; i++) {
        int idx = base + i;
        if (idx < Nc) {
            g_off[idx] = run;
            g_wr[idx]  = run;
            run += g_cnt[idx];
            g_cnt[idx] = 0;      // restore invariant for next replay
        }
    }
    if (t == 1023) g_off[Nc] = ssum[1023];
}

__global__ void k_scatter(const int* __restrict__ src, const int* __restrict__ dst, int E) {
    int e = blockIdx.x * blockDim.x + threadIdx.x;
    if (e < E) {
        int pos = atomicAdd(&g_wr[dst[e]], 1);
        g_csrc[pos] = src[e];
    }
}

// ---------------- 1: feat = x @ W via tf32 mma, single-stage full-K tiles ---
// Block: 256 threads (8 warps, 2m x 4n). Block tile 128 rows x 128 cols.
#define XS_LD 132
#define WS_LD 136
#define SMEM_GEMM ((128 * XS_LD + 128 * WS_LD + 1024) * 4)
__global__ void __launch_bounds__(256, 1)
k_gemm(const float* __restrict__ x, const float* __restrict__ W,
       const float* __restrict__ attn_l, const float* __restrict__ attn_r) {
    extern __shared__ float smem[];
    float* xs  = smem;                       // [128][XS_LD]
    float* Ws  = smem + 128 * XS_LD;         // [128][WS_LD]
    float* sEl = Ws + 128 * WS_LD;           // [128][4]
    float* sEr = sEl + 512;                  // [128][4]

    const int t = threadIdx.x;
    const int lane = t & 31, warp = t >> 5;
    const int wm = warp >> 2, wn = warp & 3;   // warp grid 2 x 4
    const int gid = lane >> 2, tig = lane & 3;
    const int row0 = blockIdx.x * 128;

    sEl[t] = 0.f; sEl[t + 256] = 0.f;
    sEr[t] = 0.f; sEr[t + 256] = 0.f;

#pragma unroll
    for (int i = 0; i < 16; i++) {
        int idx = i * 256 + t;
        int k = idx >> 5, c4 = idx & 31;
        float4 v = *(const float4*)(W + (size_t)k * 128 + c4 * 4);
        float* dstp = &Ws[k * WS_LD + c4 * 4];
        dstp[0] = __uint_as_float(f2tf32(v.x));
        dstp[1] = __uint_as_float(f2tf32(v.y));
        dstp[2] = __uint_as_float(f2tf32(v.z));
        dstp[3] = __uint_as_float(f2tf32(v.w));
    }
#pragma unroll
    for (int i = 0; i < 16; i++) {
        int idx = i * 256 + t;
        int r = idx >> 5, c4 = idx & 31;
        int grow = row0 + r;
        float4 v = make_float4(0.f, 0.f, 0.f, 0.f);
        if (grow < BNc)
            v = *(const float4*)(x + (size_t)grow * 128 + c4 * 4);
        float* dstp = &xs[r * XS_LD + c4 * 4];
        dstp[0] = __uint_as_float(f2tf32(v.x));
        dstp[1] = __uint_as_float(f2tf32(v.y));
        dstp[2] = __uint_as_float(f2tf32(v.z));
        dstp[3] = __uint_as_float(f2tf32(v.w));
    }
    __syncthreads();

    float acc[4][4][4];
#pragma unroll
    for (int i = 0; i < 4; i++)
#pragma unroll
        for (int j = 0; j < 4; j++)
#pragma unroll
            for (int r = 0; r < 4; r++) acc[i][j][r] = 0.f;

#pragma unroll
    for (int ks = 0; ks < 16; ks++) {
        const int k0 = ks * 8;
        unsigned a[4][4];
#pragma unroll
        for (int mt = 0; mt < 4; mt++) {
            int rb = wm * 64 + mt * 16;
            a[mt][0] = __float_as_uint(xs[(rb + gid) * XS_LD + k0 + tig]);
            a[mt][1] = __float_as_uint(xs[(rb + gid + 8) * XS_LD + k0 + tig]);
            a[mt][2] = __float_as_uint(xs[(rb + gid) * XS_LD + k0 + tig + 4]);
            a[mt][3] = __float_as_uint(xs[(rb + gid + 8) * XS_LD + k0 + tig + 4]);
        }
#pragma unroll
        for (int nt = 0; nt < 4; nt++) {
            int cb = wn * 32 + nt * 8;
            unsigned b0 = __float_as_uint(Ws[(k0 + tig) * WS_LD + cb + gid]);
            unsigned b1 = __float_as_uint(Ws[(k0 + tig + 4) * WS_LD + cb + gid]);
#pragma unroll
            for (int mt = 0; mt < 4; mt++)
                mma_tf32(acc[mt][nt], a[mt], b0, b1);
        }
    }

    // epilogue: store feat (fp16) + accumulate el/er into smem
#pragma unroll
    for (int mt = 0; mt < 4; mt++) {
        int lr0 = wm * 64 + mt * 16 + gid;
        int lr1 = lr0 + 8;
        float el0 = 0.f, el1 = 0.f, er0 = 0.f, er1 = 0.f;
#pragma unroll
        for (int nt = 0; nt < 4; nt++) {
            int c = wn * 32 + nt * 8 + tig * 2;
            float alc0 = attn_l[c], alc1 = attn_l[c + 1];
            float arc0 = attn_r[c], arc1 = attn_r[c + 1];
            float* a4 = acc[mt][nt];
            el0 += a4[0] * alc0 + a4[1] * alc1;
            er0 += a4[0] * arc0 + a4[1] * arc1;
            el1 += a4[2] * alc0 + a4[3] * alc1;
            er1 += a4[2] * arc0 + a4[3] * arc1;
            if (row0 + lr0 < BNc)
                *(__half2*)(g_featH + (size_t)(row0 + lr0) * 128 + c) =
                    __floats2half2_rn(a4[0], a4[1]);
            if (row0 + lr1 < BNc)
                *(__half2*)(g_featH + (size_t)(row0 + lr1) * 128 + c) =
                    __floats2half2_rn(a4[2], a4[3]);
        }
        atomicAdd(&sEl[lr0 * 4 + wn], el0);
        atomicAdd(&sEl[lr1 * 4 + wn], el1);
        atomicAdd(&sEr[lr0 * 4 + wn], er0);
        atomicAdd(&sEr[lr1 * 4 + wn], er1);
    }
    __syncthreads();
    if (t < 128 && row0 + t < BNc) {
        g_el[row0 + t] = make_float4(sEl[t * 4], sEl[t * 4 + 1], sEl[t * 4 + 2], sEl[t * 4 + 3]);
        g_er[row0 + t] = make_float4(sEr[t * 4], sEr[t * 4 + 1], sEr[t * 4 + 2], sEr[t * 4 + 3]);
    }
}

// ---------------- 2: fused edge-softmax + gather aggregation ----------------
// Sync-free: block = 2 nodes x (4 batch-warps). Warp handles (node, batch);
// lane owns 4 channels (one 8B fp16 load per edge, 256B coalesced per warp).
// Weights computed inline per lane: el/er loads are uniform per 8-lane group
// (L2 broadcast); redundant __expf is cheap MUFU overlapped with memory.
// Softmax without max-subtraction: exp(e)/sum(exp(e)) identical; |e| small.
__global__ void __launch_bounds__(256, 8) k_agg(float* __restrict__ out) {
    const int n = blockIdx.x * 2 + (threadIdx.x >> 7);
    if (n >= Nc) return;
    const int t = threadIdx.x & 127;
    const int b = t >> 5;
    const int lane = t & 31;
    const int h = lane >> 3;
    const int off0 = g_off[n];
    const int deg  = g_off[n + 1] - off0;
    const size_t nb = (size_t)b * Nc + n;

    const float er_h = ((const float*)(g_er + nb))[h];

    float a0 = 0.f, a1 = 0.f, a2 = 0.f, a3 = 0.f, wsum = 0.f;
#pragma unroll 4
    for (int j = 0; j < deg; j++) {
        int s = __ldg(&g_csrc[off0 + j]);
        float el_h = ((const float*)(g_el + (size_t)b * Nc + s))[h];
        float w = __expf(leaky(el_h + er_h, GAT_SLOPE));
        wsum += w;
        uint2 u = *(const uint2*)(g_featH + ((size_t)b * Nc + s) * 128 + lane * 4);
        float2 f0 = __half22float2(*(const __half2*)&u.x);
        float2 f1 = __half22float2(*(const __half2*)&u.y);
        a0 += w * f0.x; a1 += w * f0.y;
        a2 += w * f1.x; a3 += w * f1.y;
    }
    float inv = 1.f / fmaxf(wsum, 1e-9f);
    *(float4*)(out + nb * 128 + lane * 4) =
        make_float4(a0 * inv, a1 * inv, a2 * inv, a3 * inv);
}

// ---------------- 3: BN statistics (float4 loads) ----------------------------
__global__ void k_bnstats(const float4* __restrict__ out4) {
    int c4 = threadIdx.x & 31;                 // float4 slot within row
    int r = blockIdx.x * 8 + (threadIdx.x >> 5);
    float4 s = make_float4(0.f, 0.f, 0.f, 0.f);
    float4 q = make_float4(0.f, 0.f, 0.f, 0.f);
    for (; r < BNc; r += gridDim.x * 8) {
        float4 v = out4[(size_t)r * 32 + c4];
        s.x += v.x; s.y += v.y; s.z += v.z; s.w += v.w;
        q.x += v.x * v.x; q.y += v.y * v.y; q.z += v.z * v.z; q.w += v.w * v.w;
    }
    int c = c4 * 4;
    atomicAdd(&g_sum[c + 0], s.x); atomicAdd(&g_sum[c + 1], s.y);
    atomicAdd(&g_sum[c + 2], s.z); atomicAdd(&g_sum[c + 3], s.w);
    atomicAdd(&g_sq[c + 0], q.x);  atomicAdd(&g_sq[c + 1], q.y);
    atomicAdd(&g_sq[c + 2], q.z);  atomicAdd(&g_sq[c + 3], q.w);
}

__global__ void k_bnfinal(const float* __restrict__ gamma, const float* __restrict__ beta) {
    int c = threadIdx.x;
    float mean = g_sum[c] / (float)BNc;
    float var  = g_sq[c] / (float)BNc - mean * mean;
    float sc = gamma[c] * rsqrtf(var + BN_EPS);
    g_scale[c] = sc;
    g_shift[c] = beta[c] - mean * sc;
    g_sum[c] = 0.f;   // restore invariant for next replay
    g_sq[c]  = 0.f;
}

// ---------------- 4: BN apply + LeakyReLU (in place) -------------------------
__global__ void k_bnapply(float4* out) {
    int i = blockIdx.x * blockDim.x + threadIdx.x;
    int stride = gridDim.x * blockDim.x;
    const int n4 = BNc * HDc / 4;
    for (int p = i; p < n4; p += stride) {
        float4 v = out[p];
        int c = (p & 31) * 4;
        v.x = leaky(v.x * g_scale[c + 0] + g_shift[c + 0], ACT_SLOPE);
        v.y = leaky(v.y * g_scale[c + 1] + g_shift[c + 1], ACT_SLOPE);
        v.z = leaky(v.z * g_scale[c + 2] + g_shift[c + 2], ACT_SLOPE);
        v.w = leaky(v.w * g_scale[c + 3] + g_shift[c + 3], ACT_SLOPE);
        out[p] = v;
    }
}

// ---------------- launch -----------------------------------------------------
extern "C" void kernel_launch(void* const* d_in, const int* in_sizes, int n_in,
                              void* d_out, int out_size) {
    const float* xx     = (const float*)d_in[0];
    const float* W      = (const float*)d_in[1];
    const float* attn_l = (const float*)d_in[2];
    const float* attn_r = (const float*)d_in[3];
    const float* gamma  = (const float*)d_in[4];
    const float* beta   = (const float*)d_in[5];
    const int*   src    = (const int*)d_in[6];
    const int*   dst    = (const int*)d_in[7];
    float* out = (float*)d_out;
    const int E = in_sizes[6];

    static cudaStream_t s2 = nullptr;
    static cudaEvent_t evFork = nullptr, evJoin = nullptr;
    if (s2 == nullptr) {
        cudaStreamCreateWithFlags(&s2, cudaStreamNonBlocking);
        cudaEventCreateWithFlags(&evFork, cudaEventDisableTiming);
        cudaEventCreateWithFlags(&evJoin, cudaEventDisableTiming);
        cudaFuncSetAttribute(k_gemm, cudaFuncAttributeMaxDynamicSharedMemorySize,
                             SMEM_GEMM);
    }

    // fork: CSR build on s2, GEMM on main stream (independent work)
    cudaEventRecord(evFork, 0);
    cudaStreamWaitEvent(s2, evFork, 0);

    k_hist<<<(E + 511) / 512, 512, 0, s2>>>(dst, E);
    k_scan<<<1, 1024, 0, s2>>>();
    k_scatter<<<(E + 511) / 512, 512, 0, s2>>>(src, dst, E);
    cudaEventRecord(evJoin, s2);

    k_gemm<<<(BNc + 127) / 128, 256, SMEM_GEMM>>>(xx, W, attn_l, attn_r);

    cudaStreamWaitEvent(0, evJoin, 0);

    k_agg<<<(Nc + 1) / 2, 256>>>(out);

    k_bnstats<<<740, 256>>>((const float4*)out);
    k_bnfinal<<<1, 128>>>(gamma, beta);
    k_bnapply<<<2048, 256>>>((float4*)out);
}